// round 1
// baseline (speedup 1.0000x reference)
#include <cuda_runtime.h>
#include <cuda_bf16.h>

#define Bb 64
#define Tt 512
#define Ii 1024
#define Hh 1024

#define RNN_CTAS 128
// smem: Wsh 8*1024 + hs 4*128*64 + red 4*512  (floats)
#define RNN_SMEM_FLOATS (8*1024 + 4*128*64 + 4*512)
#define RNN_SMEM_BYTES (RNN_SMEM_FLOATS * 4)

__device__ __align__(16) float g_Wih[Hh * Ii];
__device__ __align__(16) float g_Whh[Hh * Hh];
__device__ __align__(16) float g_bias[Hh];
__device__ __align__(16) float g_hT[2 * Hh * Bb];   // double-buffered h, transposed [k][b]
__device__ unsigned g_count;

__device__ __forceinline__ float hc_gate(float x) {
    float s = 1.0f / (1.0f + expf(-x));
    float v = s * 1.2f - 0.1f;           // limit_b - limit_a = 1.2, + limit_a
    return fminf(fmaxf(v, 0.0f), 1.0f);
}

// ---------------------------------------------------------------------------
// Phase 1: gate weights, gated-bias sum, zero h0, reset barrier counter
// ---------------------------------------------------------------------------
__global__ void regrnn_prep(const float* __restrict__ w_ih, const float* __restrict__ w_ih_mask,
                            const float* __restrict__ w_hh, const float* __restrict__ w_hh_mask,
                            const float* __restrict__ b_ih, const float* __restrict__ b_ih_mask,
                            const float* __restrict__ b_hh, const float* __restrict__ b_hh_mask) {
    int i = blockIdx.x * blockDim.x + threadIdx.x;
    if (i < Hh * Ii) {
        g_Wih[i] = hc_gate(w_ih_mask[i]) * w_ih[i];
        g_Whh[i] = hc_gate(w_hh_mask[i]) * w_hh[i];
    }
    if (i < Hh) {
        g_bias[i] = hc_gate(b_ih_mask[i]) * b_ih[i] + hc_gate(b_hh_mask[i]) * b_hh[i];
    }
    if (i < 2 * Hh * Bb) g_hT[i] = 0.0f;
    if (i == 0) g_count = 0u;
}

// ---------------------------------------------------------------------------
// Phase 2: x_proj GEMM: out[m][n] = sum_k seq[m][k] * g_Wih[n][k] + g_bias[n]
// m = b*T + t (32768), n = H (1024), k = I (1024). Written in-place into d_out.
// 64x64 tile, TK=32, 256 threads, 4x4 register tile.
// ---------------------------------------------------------------------------
__global__ void __launch_bounds__(256) regrnn_xproj(const float* __restrict__ A,
                                                    float* __restrict__ out) {
    __shared__ __align__(16) float As[32][64];
    __shared__ __align__(16) float Bs[32][64];
    const int m0 = blockIdx.y * 64;
    const int n0 = blockIdx.x * 64;
    const int t = threadIdx.x;
    const int tx = t & 15;    // n quad
    const int ty = t >> 4;    // m quad

    float acc[4][4];
#pragma unroll
    for (int i = 0; i < 4; i++)
#pragma unroll
        for (int j = 0; j < 4; j++) acc[i][j] = 0.0f;

    for (int kt = 0; kt < Ii; kt += 32) {
        // stage A and B tiles transposed: As[k][m], Bs[k][n]
#pragma unroll
        for (int f0 = 0; f0 < 2; f0++) {
            int f = t + f0 * 256;        // 0..511 float4 slots
            int m = f >> 3;              // 0..63
            int k4 = (f & 7) << 2;       // 0,4,...,28
            float4 va = *(const float4*)(A + (m0 + m) * Ii + kt + k4);
            As[k4 + 0][m] = va.x; As[k4 + 1][m] = va.y;
            As[k4 + 2][m] = va.z; As[k4 + 3][m] = va.w;
            float4 vb = *(const float4*)(g_Wih + (n0 + m) * Ii + kt + k4);
            Bs[k4 + 0][m] = vb.x; Bs[k4 + 1][m] = vb.y;
            Bs[k4 + 2][m] = vb.z; Bs[k4 + 3][m] = vb.w;
        }
        __syncthreads();
#pragma unroll 8
        for (int kk = 0; kk < 32; kk++) {
            float4 a = *(const float4*)&As[kk][ty << 2];
            float4 b = *(const float4*)&Bs[kk][tx << 2];
            acc[0][0] += a.x * b.x; acc[0][1] += a.x * b.y; acc[0][2] += a.x * b.z; acc[0][3] += a.x * b.w;
            acc[1][0] += a.y * b.x; acc[1][1] += a.y * b.y; acc[1][2] += a.y * b.z; acc[1][3] += a.y * b.w;
            acc[2][0] += a.z * b.x; acc[2][1] += a.z * b.y; acc[2][2] += a.z * b.z; acc[2][3] += a.z * b.w;
            acc[3][0] += a.w * b.x; acc[3][1] += a.w * b.y; acc[3][2] += a.w * b.z; acc[3][3] += a.w * b.w;
        }
        __syncthreads();
    }

    const int n = n0 + (tx << 2);
    float b0 = g_bias[n + 0], b1 = g_bias[n + 1], b2 = g_bias[n + 2], b3 = g_bias[n + 3];
#pragma unroll
    for (int i = 0; i < 4; i++) {
        int m = m0 + (ty << 2) + i;
        float4 r;
        r.x = acc[i][0] + b0; r.y = acc[i][1] + b1;
        r.z = acc[i][2] + b2; r.w = acc[i][3] + b3;
        *(float4*)(out + (size_t)m * Hh + n) = r;
    }
}

// ---------------------------------------------------------------------------
// Phase 3: persistent recurrence. 128 CTAs x 256 threads.
// CTA owns 8 output columns; W slice resident in SMEM for all 512 steps.
// h kept transposed in global (double buffered): g_hT[buf][k][b].
// Thread decomposition: kg (4 K-split groups) x cp (4 col-pairs) x bq (16 b-quads).
// ---------------------------------------------------------------------------
__global__ void __launch_bounds__(256) regrnn_rnn(float* __restrict__ out) {
    extern __shared__ __align__(16) float sm[];
    float* Wsh = sm;                        // [1024][8] : W_hh[c][k] transposed to [k][ci]
    float* hs  = sm + 8 * 1024;             // [4][128][64]
    float* red = hs + 4 * 128 * 64;         // [4][512]

    const int t = threadIdx.x;
    const int C0 = blockIdx.x * 8;

    // load W slice (once): Wsh[k*8 + ci] = g_Whh[(C0+ci)*1024 + k]
    for (int i = t; i < 8 * 1024; i += 256) {
        int ci = i >> 10;
        int k = i & 1023;
        Wsh[k * 8 + ci] = g_Whh[(C0 + ci) * Ii + k];
    }

    const int kg = t >> 6;          // 0..3  K-split group
    const int idx = t & 63;
    const int cp = idx >> 4;        // 0..3  column pair
    const int bq = idx & 15;        // 0..15 batch quad
    __syncthreads();

    for (int step = 0; step < Tt; step++) {
        const float* hsrc = g_hT + (step & 1) * (Hh * Bb);
        float* hdst = g_hT + ((step & 1) ^ 1) * (Hh * Bb);

        float acc[2][4] = {{0.f, 0.f, 0.f, 0.f}, {0.f, 0.f, 0.f, 0.f}};

#pragma unroll 1
        for (int cc = 0; cc < 2; cc++) {
            const int base = kg * 256 + cc * 128;
            // stage this group's 128x64 h chunk (coherent L2 reads)
#pragma unroll
            for (int r = 0; r < 32; r++) {
                int fid = (r << 6) + idx;         // 0..2047 float4 slots
                int kk = fid >> 4;                // 0..127
                int b4 = (fid & 15) << 2;
                float4 v = __ldcg((const float4*)(hsrc + (base + kk) * Bb + b4));
                *(float4*)&hs[((kg << 7) + kk) * 64 + b4] = v;
            }
            __syncthreads();
#pragma unroll 8
            for (int kk = 0; kk < 128; kk++) {
                float2 w = *(const float2*)&Wsh[(base + kk) * 8 + (cp << 1)];
                float4 h4 = *(const float4*)&hs[((kg << 7) + kk) * 64 + (bq << 2)];
                acc[0][0] += w.x * h4.x; acc[0][1] += w.x * h4.y;
                acc[0][2] += w.x * h4.z; acc[0][3] += w.x * h4.w;
                acc[1][0] += w.y * h4.x; acc[1][1] += w.y * h4.y;
                acc[1][2] += w.y * h4.z; acc[1][3] += w.y * h4.w;
            }
            __syncthreads();
        }

        // write K-split partials to smem
        {
            int ob = (cp << 1) * 64 + (bq << 2);
#pragma unroll
            for (int ci = 0; ci < 2; ci++)
#pragma unroll
                for (int bi = 0; bi < 4; bi++)
                    red[(kg << 9) + ob + (ci << 6) + bi] = acc[ci][bi];
        }
        __syncthreads();

        // reduce 4 partials + x_proj, tanh, write out + next h (2 outputs/thread)
#pragma unroll
        for (int oo = 0; oo < 2; oo++) {
            int o = t + (oo << 8);
            int ci = o >> 6;
            int b = o & 63;
            float v = red[o] + red[512 + o] + red[1024 + o] + red[1536 + o];
            int c = C0 + ci;
            int xi = (b * Tt + step) * Hh + c;
            float hv = tanhf(out[xi] + v);
            out[xi] = hv;
            __stcg(hdst + c * Bb + b, hv);
            if (step == Tt - 1) out[Bb * Tt * Hh + b * Hh + c] = hv;
        }

        // grid barrier (monotonic count; reset by prep each launch)
        __threadfence();
        __syncthreads();
        if (t == 0) {
            atomicAdd(&g_count, 1u);
            unsigned target = (unsigned)gridDim.x * (unsigned)(step + 1);
            while (*(volatile unsigned*)&g_count < target) { }
        }
        __syncthreads();
    }
}

// ---------------------------------------------------------------------------
extern "C" void kernel_launch(void* const* d_in, const int* in_sizes, int n_in,
                              void* d_out, int out_size) {
    (void)in_sizes; (void)n_in; (void)out_size;
    const float* seq       = (const float*)d_in[0];
    const float* w_ih      = (const float*)d_in[1];
    const float* w_ih_mask = (const float*)d_in[2];
    const float* w_hh      = (const float*)d_in[3];
    const float* w_hh_mask = (const float*)d_in[4];
    const float* b_ih      = (const float*)d_in[5];
    const float* b_ih_mask = (const float*)d_in[6];
    const float* b_hh      = (const float*)d_in[7];
    const float* b_hh_mask = (const float*)d_in[8];
    float* out = (float*)d_out;

    regrnn_prep<<<(Hh * Ii + 255) / 256, 256>>>(w_ih, w_ih_mask, w_hh, w_hh_mask,
                                                b_ih, b_ih_mask, b_hh, b_hh_mask);
    regrnn_xproj<<<dim3(Hh / 64, (Bb * Tt) / 64), 256>>>(seq, out);

    cudaFuncSetAttribute(regrnn_rnn, cudaFuncAttributeMaxDynamicSharedMemorySize, RNN_SMEM_BYTES);
    regrnn_rnn<<<RNN_CTAS, 256, RNN_SMEM_BYTES>>>(out);
}

// round 2
// speedup vs baseline: 1.5925x; 1.5925x over previous
#include <cuda_runtime.h>
#include <cuda_bf16.h>
#include <cstdint>

#define Bb 64
#define Tt 512
#define Ii 1024
#define Hh 1024

#define RNN_CTAS 128
// smem floats: Wsh 8192 + hs 8*2*2048=32768 + red 8*512=4096
#define RNN_SMEM_BYTES ((8192 + 32768 + 4096) * 4)

__device__ __align__(16) float g_Wih[Hh * Ii];
__device__ __align__(16) float g_Whh[Hh * Hh];
__device__ __align__(16) float g_bias[Hh];
__device__ __align__(16) float g_hT[2 * Hh * Bb];   // double-buffered h, [k][b]
__device__ unsigned g_count;

typedef unsigned long long u64t;

__device__ __forceinline__ u64t pack2(float x, float y) {
    u64t r; asm("mov.b64 %0, {%1,%2};" : "=l"(r) : "f"(x), "f"(y)); return r;
}
__device__ __forceinline__ u64t fma2(u64t a, u64t b, u64t c) {
    u64t d; asm("fma.rn.f32x2 %0, %1, %2, %3;" : "=l"(d) : "l"(a), "l"(b), "l"(c)); return d;
}
__device__ __forceinline__ u64t add2(u64t a, u64t b) {
    u64t d; asm("add.rn.f32x2 %0, %1, %2;" : "=l"(d) : "l"(a), "l"(b)); return d;
}

__device__ __forceinline__ void cpasync16(uint32_t dst, const void* src) {
    asm volatile("cp.async.cg.shared.global [%0], [%1], 16;" :: "r"(dst), "l"(src));
}
#define CP_COMMIT() asm volatile("cp.async.commit_group;")

__device__ __forceinline__ float hc_gate(float x) {
    float s = 1.0f / (1.0f + expf(-x));
    float v = s * 1.2f - 0.1f;
    return fminf(fmaxf(v, 0.0f), 1.0f);
}

// ---------------------------------------------------------------------------
// Phase 1: gate weights, gated-bias sum, zero h0, reset barrier counter
// ---------------------------------------------------------------------------
__global__ void regrnn_prep(const float* __restrict__ w_ih, const float* __restrict__ w_ih_mask,
                            const float* __restrict__ w_hh, const float* __restrict__ w_hh_mask,
                            const float* __restrict__ b_ih, const float* __restrict__ b_ih_mask,
                            const float* __restrict__ b_hh, const float* __restrict__ b_hh_mask) {
    int i = blockIdx.x * blockDim.x + threadIdx.x;
    if (i < Hh * Ii) {
        g_Wih[i] = hc_gate(w_ih_mask[i]) * w_ih[i];
        g_Whh[i] = hc_gate(w_hh_mask[i]) * w_hh[i];
    }
    if (i < Hh) {
        g_bias[i] = hc_gate(b_ih_mask[i]) * b_ih[i] + hc_gate(b_hh_mask[i]) * b_hh[i];
    }
    if (i < 2 * Hh * Bb) g_hT[i] = 0.0f;
    if (i == 0) g_count = 0u;
}

// ---------------------------------------------------------------------------
// Phase 2: x_proj GEMM, f32x2 packed. out[m][n] = seq[m][:]·Wih[n][:] + bias[n]
// Tile 128(m) x 64(n), K-tile 16, 256 threads, micro 4m x 8n.
// ---------------------------------------------------------------------------
__global__ void __launch_bounds__(256) regrnn_xproj(const float* __restrict__ A,
                                                    float* __restrict__ out) {
    __shared__ __align__(16) float As[16][132];
    __shared__ __align__(16) float Bs[16][68];
    const int m0 = blockIdx.y * 128;
    const int n0 = blockIdx.x * 64;
    const int t = threadIdx.x;
    const int tx = t & 7;     // n-octet
    const int ty = t >> 3;    // m-quad (0..31)

    u64t acc[4][4];
#pragma unroll
    for (int i = 0; i < 4; i++)
#pragma unroll
        for (int j = 0; j < 4; j++) acc[i][j] = 0ULL;

    for (int kt = 0; kt < Ii; kt += 16) {
        // stage A (128x16) transposed
#pragma unroll
        for (int i = 0; i < 2; i++) {
            int f = t + 256 * i;
            int m = f >> 2;
            int k4 = (f & 3) << 2;
            float4 v = *(const float4*)(A + (size_t)(m0 + m) * Ii + kt + k4);
            As[k4 + 0][m] = v.x; As[k4 + 1][m] = v.y;
            As[k4 + 2][m] = v.z; As[k4 + 3][m] = v.w;
        }
        // stage B (64x16) transposed
        {
            int n = t >> 2;
            int k4 = (t & 3) << 2;
            float4 v = *(const float4*)(g_Wih + (size_t)(n0 + n) * Ii + kt + k4);
            Bs[k4 + 0][n] = v.x; Bs[k4 + 1][n] = v.y;
            Bs[k4 + 2][n] = v.z; Bs[k4 + 3][n] = v.w;
        }
        __syncthreads();
#pragma unroll
        for (int kk = 0; kk < 16; kk++) {
            float4 a4 = *(const float4*)&As[kk][ty << 2];
            ulonglong2 b01 = *(const ulonglong2*)&Bs[kk][tx << 3];
            ulonglong2 b23 = *(const ulonglong2*)&Bs[kk][(tx << 3) + 4];
            u64t s0 = pack2(a4.x, a4.x);
            u64t s1 = pack2(a4.y, a4.y);
            u64t s2 = pack2(a4.z, a4.z);
            u64t s3 = pack2(a4.w, a4.w);
            acc[0][0] = fma2(s0, b01.x, acc[0][0]); acc[0][1] = fma2(s0, b01.y, acc[0][1]);
            acc[0][2] = fma2(s0, b23.x, acc[0][2]); acc[0][3] = fma2(s0, b23.y, acc[0][3]);
            acc[1][0] = fma2(s1, b01.x, acc[1][0]); acc[1][1] = fma2(s1, b01.y, acc[1][1]);
            acc[1][2] = fma2(s1, b23.x, acc[1][2]); acc[1][3] = fma2(s1, b23.y, acc[1][3]);
            acc[2][0] = fma2(s2, b01.x, acc[2][0]); acc[2][1] = fma2(s2, b01.y, acc[2][1]);
            acc[2][2] = fma2(s2, b23.x, acc[2][2]); acc[2][3] = fma2(s2, b23.y, acc[2][3]);
            acc[3][0] = fma2(s3, b01.x, acc[3][0]); acc[3][1] = fma2(s3, b01.y, acc[3][1]);
            acc[3][2] = fma2(s3, b23.x, acc[3][2]); acc[3][3] = fma2(s3, b23.y, acc[3][3]);
        }
        __syncthreads();
    }

    const int n = n0 + (tx << 3);
    ulonglong2 bv0 = *(const ulonglong2*)(g_bias + n);
    ulonglong2 bv1 = *(const ulonglong2*)(g_bias + n + 4);
#pragma unroll
    for (int i = 0; i < 4; i++) {
        int m = m0 + (ty << 2) + i;
        ulonglong2 st0, st1;
        st0.x = add2(acc[i][0], bv0.x); st0.y = add2(acc[i][1], bv0.y);
        st1.x = add2(acc[i][2], bv1.x); st1.y = add2(acc[i][3], bv1.y);
        *(ulonglong2*)(out + (size_t)m * Hh + n) = st0;
        *(ulonglong2*)(out + (size_t)m * Hh + n + 4) = st1;
    }
}

// ---------------------------------------------------------------------------
// Phase 3: persistent recurrence. 128 CTAs x 256 threads (8 warps).
// Warp = K-split group of 128 k; each warp computes all 8x64 outputs (partial).
// h staged per-warp via cp.async.cg in 4 double-buffered rounds of 32 k.
// Thread micro: 2 cols (cp pair) x 8 batches (bo octet), f32x2 packed.
// ---------------------------------------------------------------------------
__global__ void __launch_bounds__(256) regrnn_rnn(float* __restrict__ out) {
    extern __shared__ __align__(16) float sm[];
    float* Wsh = sm;                 // [1024][8]
    float* hsAll = sm + 8192;        // 8 warps x 2 bufs x (32k x 64b)
    float* red = sm + 8192 + 32768;  // [8][512]

    const int t = threadIdx.x;
    const int w = t >> 5;
    const int lane = t & 31;
    const int C0 = blockIdx.x * 8;

    // W slice transposed into smem (resident all 512 steps)
    for (int i = t; i < 8 * 1024; i += 256) {
        int ci = i >> 10;
        int k = i & 1023;
        Wsh[k * 8 + ci] = g_Whh[(C0 + ci) * Ii + k];
    }

    const int cp = lane >> 3;        // col pair 0..3
    const int bo = lane & 7;         // batch octet 0..7
    float* hw = hsAll + w * 4096;    // this warp's 2 buffers
    uint32_t hw_u32 = (uint32_t)__cvta_generic_to_shared(hw);
    const int kbase = w * 128;

    // reduction/epilogue indices (2 consecutive outputs per thread)
    const int o0 = 2 * t;            // 0..510
    const int cl = o0 >> 6;          // 0..7
    const int bb = o0 & 63;          // even
    const int c_g = C0 + cl;

    __syncthreads();

    for (int step = 0; step < Tt; step++) {
        const float* hsrc = g_hT + (step & 1) * (Hh * Bb);
        float* hdst = g_hT + ((step & 1) ^ 1) * (Hh * Bb);

        // prefetch x_proj values (independent of h)
        const int xi0 = (bb * Tt + step) * Hh + c_g;
        const int xi1 = ((bb + 1) * Tt + step) * Hh + c_g;
        float xp0 = out[xi0];
        float xp1 = out[xi1];

        // ---- stage rounds 0,1 ----
#pragma unroll
        for (int r = 0; r < 2; r++) {
#pragma unroll
            for (int i = 0; i < 16; i++) {
                int fid = lane + (i << 5);
                int kk = fid >> 4;
                int b4 = (fid & 15) << 2;
                cpasync16(hw_u32 + (((r & 1) * 2048 + kk * 64 + b4) << 2),
                          hsrc + (kbase + r * 32 + kk) * Bb + b4);
            }
            CP_COMMIT();
        }

        u64t a0[4] = {0ULL, 0ULL, 0ULL, 0ULL};
        u64t a1[4] = {0ULL, 0ULL, 0ULL, 0ULL};

#pragma unroll
        for (int r = 0; r < 4; r++) {
            if (r < 3) asm volatile("cp.async.wait_group 1;");
            else       asm volatile("cp.async.wait_group 0;");
            __syncwarp();
            const float* hb = hw + (r & 1) * 2048;
            const int kr = kbase + r * 32;
#pragma unroll 8
            for (int kk = 0; kk < 32; kk++) {
                float2 w2 = *(const float2*)&Wsh[(kr + kk) * 8 + (cp << 1)];
                ulonglong2 h01 = *(const ulonglong2*)&hb[kk * 64 + (bo << 3)];
                ulonglong2 h23 = *(const ulonglong2*)&hb[kk * 64 + (bo << 3) + 4];
                u64t sx = pack2(w2.x, w2.x);
                u64t sy = pack2(w2.y, w2.y);
                a0[0] = fma2(sx, h01.x, a0[0]); a0[1] = fma2(sx, h01.y, a0[1]);
                a0[2] = fma2(sx, h23.x, a0[2]); a0[3] = fma2(sx, h23.y, a0[3]);
                a1[0] = fma2(sy, h01.x, a1[0]); a1[1] = fma2(sy, h01.y, a1[1]);
                a1[2] = fma2(sy, h23.x, a1[2]); a1[3] = fma2(sy, h23.y, a1[3]);
            }
            if (r < 2) {
                const int rn = r + 2;
#pragma unroll
                for (int i = 0; i < 16; i++) {
                    int fid = lane + (i << 5);
                    int kk = fid >> 4;
                    int b4 = (fid & 15) << 2;
                    cpasync16(hw_u32 + (((rn & 1) * 2048 + kk * 64 + b4) << 2),
                              hsrc + (kbase + rn * 32 + kk) * Bb + b4);
                }
                CP_COMMIT();
            }
        }

        // write K-split partials: red[w][c_local][b]
        {
            float* rw = red + w * 512;
            int rb = (cp << 1) * 64 + (bo << 3);
#pragma unroll
            for (int j = 0; j < 4; j++) *(u64t*)&rw[rb + 2 * j] = a0[j];
#pragma unroll
            for (int j = 0; j < 4; j++) *(u64t*)&rw[rb + 64 + 2 * j] = a1[j];
        }
        __syncthreads();

        // reduce 8 partials, tanh, write next h
        float sx = 0.0f, sy = 0.0f;
#pragma unroll
        for (int ww = 0; ww < 8; ww++) {
            float2 v = *(const float2*)&red[ww * 512 + o0];
            sx += v.x; sy += v.y;
        }
        float hv0 = tanhf(xp0 + sx);
        float hv1 = tanhf(xp1 + sy);
        __stcg((float2*)(hdst + c_g * Bb + bb), make_float2(hv0, hv1));

        __threadfence();
        __syncthreads();
        if (t == 0) {
            atomicAdd(&g_count, 1u);
            unsigned target = (unsigned)gridDim.x * (unsigned)(step + 1);
            while (*(volatile unsigned*)&g_count < target) { }
        }
        // overlap out writes with t0's spin
        out[xi0] = hv0;
        out[xi1] = hv1;
        if (step == Tt - 1) {
            out[Bb * Tt * Hh + bb * Hh + c_g] = hv0;
            out[Bb * Tt * Hh + (bb + 1) * Hh + c_g] = hv1;
        }
        __syncthreads();
    }
}

// ---------------------------------------------------------------------------
extern "C" void kernel_launch(void* const* d_in, const int* in_sizes, int n_in,
                              void* d_out, int out_size) {
    (void)in_sizes; (void)n_in; (void)out_size;
    const float* seq       = (const float*)d_in[0];
    const float* w_ih      = (const float*)d_in[1];
    const float* w_ih_mask = (const float*)d_in[2];
    const float* w_hh      = (const float*)d_in[3];
    const float* w_hh_mask = (const float*)d_in[4];
    const float* b_ih      = (const float*)d_in[5];
    const float* b_ih_mask = (const float*)d_in[6];
    const float* b_hh      = (const float*)d_in[7];
    const float* b_hh_mask = (const float*)d_in[8];
    float* out = (float*)d_out;

    regrnn_prep<<<(Hh * Ii + 255) / 256, 256>>>(w_ih, w_ih_mask, w_hh, w_hh_mask,
                                                b_ih, b_ih_mask, b_hh, b_hh_mask);
    regrnn_xproj<<<dim3(Hh / 64, (Bb * Tt) / 128), 256>>>(seq, out);

    cudaFuncSetAttribute(regrnn_rnn, cudaFuncAttributeMaxDynamicSharedMemorySize, RNN_SMEM_BYTES);
    regrnn_rnn<<<RNN_CTAS, 256, RNN_SMEM_BYTES>>>(out);
}